// round 6
// baseline (speedup 1.0000x reference)
#include <cuda_runtime.h>
#include <cuda_fp16.h>
#include <cstdint>
#include <cstddef>

#define KTOT 4096

// T precomputed in fp16: 2048 rows x 4096 (u,v) cols.
__device__ __half g_T[2048 * KTOT];

__device__ __forceinline__ uint32_t smem_u32(const void* p) {
    uint32_t a;
    asm("{ .reg .u64 t; cvta.to.shared.u64 t, %1; cvt.u32.u64 %0, t; }" : "=r"(a) : "l"(p));
    return a;
}
#define CP_ASYNC16(dst, src) \
    asm volatile("cp.async.cg.shared.global [%0], [%1], 16;" :: "r"(dst), "l"(src) : "memory")
#define CP_COMMIT() asm volatile("cp.async.commit_group;" ::: "memory")
#define CP_WAIT0()  asm volatile("cp.async.wait_group 0;" ::: "memory")
#define LDSM_X4(r, addr) \
    asm volatile("ldmatrix.sync.aligned.m8n8.x4.shared.b16 {%0,%1,%2,%3}, [%4];" \
        : "=r"((r)[0]), "=r"((r)[1]), "=r"((r)[2]), "=r"((r)[3]) : "r"(addr))
#define LDSM_X4_T(r, addr) \
    asm volatile("ldmatrix.sync.aligned.m8n8.x4.trans.shared.b16 {%0,%1,%2,%3}, [%4];" \
        : "=r"((r)[0]), "=r"((r)[1]), "=r"((r)[2]), "=r"((r)[3]) : "r"(addr))
#define MMA16816(d, a, b) \
    asm volatile("mma.sync.aligned.m16n8k16.row.col.f32.f16.f16.f32 " \
        "{%0,%1,%2,%3}, {%4,%5,%6,%7}, {%8,%9}, {%0,%1,%2,%3};" \
        : "+f"((d)[0]), "+f"((d)[1]), "+f"((d)[2]), "+f"((d)[3]) \
        : "r"((a)[0]), "r"((a)[1]), "r"((a)[2]), "r"((a)[3]), "r"((b)[0]), "r"((b)[1]))

// ---------------- precompute T (fp16) ----------------
__global__ void precompute_T(const float* __restrict__ x1, const float* __restrict__ x2) {
    __shared__ float sa0[64], sb0[64], sa1[192], sb1[192];
    int b = blockIdx.x, tid = threadIdx.x;
    if (tid < 64) { sa0[tid] = x1[b * 256 + tid]; sb0[tid] = x2[b * 256 + tid]; }
    else { int j = tid - 64; sa1[j] = x1[b * 256 + 64 + j]; sb1[j] = x2[b * 256 + 64 + j]; }
    __syncthreads();

    const float C1 = 0.011048543456039806f;    // 1/sqrt(8192)
    const float C2 = -0.0063788657f;           // -1/sqrt(3*8192)
    const float IS2 = 0.70710678118654752f;
    const float IS6 = 0.40824829046386302f;
    const float INV64 = 0.015625f;

    for (int uv = tid; uv < KTOT; uv += blockDim.x) {
        int u = uv >> 6, v = uv & 63;
        float a0 = sa0[u], b0 = sb0[v];
        float av[3], bv[3];
#pragma unroll
        for (int i = 0; i < 3; i++) { av[i] = sa1[u * 3 + i]; bv[i] = sb1[v * 3 + i]; }
        __half* T = g_T + uv;
        T[(size_t)(0 + b) * KTOT]   = __float2half_rn(C1 * a0 * b0);
        T[(size_t)(128 + b) * KTOT] = __float2half_rn(C2 * (av[0]*bv[0] + av[1]*bv[1] + av[2]*bv[2]));
#pragma unroll
        for (int k = 0; k < 3; k++) {
            int k1 = (k + 1) % 3, k2 = (k + 2) % 3;
            T[(size_t)(256 + k * 128 + b) * KTOT]  = __float2half_rn(C1 * a0 * bv[k]);
            T[(size_t)(640 + k * 128 + b) * KTOT]  = __float2half_rn(C1 * av[k] * b0);
            T[(size_t)(1024 + k * 128 + b) * KTOT] = __float2half_rn(-C1 * (av[k1]*bv[k2] - av[k2]*bv[k1]));
        }
        float q[5];
        q[0] = IS2 * (av[0]*bv[2] + av[2]*bv[0]);
        q[1] = IS2 * (av[0]*bv[1] + av[1]*bv[0]);
        q[2] = IS6 * (2.0f*av[1]*bv[1] - av[0]*bv[0] - av[2]*bv[2]);
        q[3] = IS2 * (av[1]*bv[2] + av[2]*bv[1]);
        q[4] = IS2 * (av[2]*bv[2] - av[0]*bv[0]);
#pragma unroll
        for (int k = 0; k < 5; k++)
            T[(size_t)(1408 + k * 128 + b) * KTOT] = __float2half_rn(INV64 * q[k]);
    }
}

// ---------------- HMMA GEMM ----------------
// smem (dynamic, bytes):
//   As  @0     : 2 stages x 128 rows x 80B  (32 halves + 8 pad)  = 20480
//   B16 @20480 : 2 stages x 32 rows x 272B (128 halves + 8 pad)  = 17408
#define SM_A   0
#define SM_B16 20480
#define SMEM_BYTES 37888
#define KC 32

__global__ void __launch_bounds__(256, 2)
tp_gemm(const float* __restrict__ w1, const float* __restrict__ w2,
        const float* __restrict__ w3, const float* __restrict__ w4,
        const float* __restrict__ w5, const float* __restrict__ w6,
        float* __restrict__ out) {
    extern __shared__ char smem[];
    uint32_t sb = smem_u32(smem);
    int tid = threadIdx.x, wid = tid >> 5, lane = tid & 31;
    int warpM = wid >> 2, warpN = wid & 3;

    // ---- decode work ----
    int bid = blockIdx.x;
    int npass, trow0, trow1 = 0, Ngrp, n0, obase, ncomp, kc;
    const float *Wa, *Wb = nullptr;
    if (bid < 64) {                 // o0: 1x64 tiles, w1+w2
        npass = 2; trow0 = 0; trow1 = 128; Wa = w1; Wb = w2;
        Ngrp = 8192; n0 = bid * 128; obase = 0; ncomp = 1; kc = 0;
    } else if (bid < 256) {         // o1: 3x64 tiles, w3+w4
        int r = bid - 64; int nt = r / 3, mt = r % 3;
        npass = 2; trow0 = 256 + mt * 128; trow1 = 640 + mt * 128; Wa = w3; Wb = w4;
        Ngrp = 8192; n0 = nt * 128; obase = 8192; ncomp = 3; kc = mt;
    } else if (bid < 352) {         // o1e: 3x32 tiles, w5
        int r = bid - 256; int nt = r / 3, mt = r % 3;
        npass = 1; trow0 = 1024 + mt * 128; Wa = w5;
        Ngrp = 4096; n0 = nt * 128; obase = 32768; ncomp = 3; kc = mt;
    } else {                        // o2e: 5x32 tiles, w6
        int r = bid - 352; int nt = r / 5, mt = r % 5;
        npass = 1; trow0 = 1408 + mt * 128; Wa = w6;
        Ngrp = 4096; n0 = nt * 128; obase = 45056; ncomp = 5; kc = mt;
    }
    int nch = npass * (KTOT / KC);  // 128 or 256

    // per-thread fixed B load/store coords
    int brow = tid >> 3;            // 0..31 (k row), 8 threads cover 128 floats
    int bcol = (tid & 7) * 16;      // float col: 16 floats per thread (4 float4)

    // ---- A async load of one chunk into stage s ----
    auto issue_A = [&](int chunk, int s) {
        int pass = chunk >> 7;
        int k0 = (chunk & 127) * KC;
        int trow = pass ? trow1 : trow0;
#pragma unroll
        for (int it = 0; it < 2; it++) {
            int idx = tid + it * 256;
            int row = idx >> 2, c = idx & 3;
            const void* src = g_T + ((size_t)(trow + row) * KTOT + k0 + c * 8);
            CP_ASYNC16(sb + SM_A + s * 10240 + row * 80 + c * 16, src);
        }
        CP_COMMIT();
    };
    // ---- B: LDG fp32 into regs ----
    auto load_B = [&](int chunk, float4* br) {
        int pass = chunk >> 7;
        int k0 = (chunk & 127) * KC;
        const float* W = pass ? Wb : Wa;
        const float* p = W + (size_t)(k0 + brow) * Ngrp + n0 + bcol;
#pragma unroll
        for (int it = 0; it < 4; it++)
            br[it] = *(const float4*)(p + it * 4);
    };
    // ---- B: cvt + STS into stage s ----
    auto store_B = [&](int s, const float4* br) {
        char* dst = smem + SM_B16 + s * 8704 + brow * 272 + bcol * 2;
#pragma unroll
        for (int it = 0; it < 4; it++) {
            __half2 h0 = __floats2half2_rn(br[it].x, br[it].y);
            __half2 h1 = __floats2half2_rn(br[it].z, br[it].w);
            uint2 v; v.x = *(uint32_t*)&h0; v.y = *(uint32_t*)&h1;
            *(uint2*)(dst + it * 8) = v;
        }
    };

    float acc[4][4][4];
#pragma unroll
    for (int i = 0; i < 4; i++)
#pragma unroll
        for (int j = 0; j < 4; j++)
#pragma unroll
            for (int c = 0; c < 4; c++) acc[i][j][c] = 0.0f;

    float4 breg[4];

    // prologue: chunk 0 into stage 0
    load_B(0, breg);
    issue_A(0, 0);
    store_B(0, breg);
    CP_WAIT0();
    __syncthreads();

    for (int i = 0; i < nch; i++) {
        int s = i & 1;
        // start next chunk's loads (A async into s^1, B into regs)
        if (i + 1 < nch) {
            load_B(i + 1, breg);
            issue_A(i + 1, s ^ 1);
        }
        // compute current chunk
        uint32_t aBase = sb + SM_A + s * 10240;
        uint32_t bBase = sb + SM_B16 + s * 8704;
#pragma unroll
        for (int k16 = 0; k16 < 2; k16++) {
            uint32_t afr[4][4], bfr[2][4];
#pragma unroll
            for (int mi = 0; mi < 4; mi++)
                LDSM_X4(afr[mi], aBase + (warpM * 64 + mi * 16 + (lane & 15)) * 80
                                       + k16 * 32 + (lane >> 4) * 16);
#pragma unroll
            for (int ni = 0; ni < 2; ni++)
                LDSM_X4_T(bfr[ni], bBase + (k16 * 16 + (lane & 15)) * 272
                                        + (warpN * 32 + ni * 16 + (lane >> 4) * 8) * 2);
#pragma unroll
            for (int mi = 0; mi < 4; mi++)
#pragma unroll
                for (int j = 0; j < 4; j++)
                    MMA16816(acc[mi][j], afr[mi], &bfr[j >> 1][(j & 1) * 2]);
        }
        if (i + 1 < nch) {
            store_B(s ^ 1, breg);
            CP_WAIT0();
        }
        __syncthreads();
    }

    // ---- epilogue: acc -> out ----
#pragma unroll
    for (int mi = 0; mi < 4; mi++) {
        int r0 = warpM * 64 + mi * 16 + (lane >> 2);   // = batch index b
#pragma unroll
        for (int j = 0; j < 4; j++) {
            int n = n0 + warpN * 32 + j * 8 + (lane & 3) * 2;
            size_t b0 = (size_t)r0 * 65536 + obase + kc;
            size_t b1 = (size_t)(r0 + 8) * 65536 + obase + kc;
            out[b0 + (size_t)n * ncomp]       = acc[mi][j][0];
            out[b0 + (size_t)(n + 1) * ncomp] = acc[mi][j][1];
            out[b1 + (size_t)n * ncomp]       = acc[mi][j][2];
            out[b1 + (size_t)(n + 1) * ncomp] = acc[mi][j][3];
        }
    }
}

extern "C" void kernel_launch(void* const* d_in, const int* in_sizes, int n_in,
                              void* d_out, int out_size) {
    const float* x1 = (const float*)d_in[0];
    const float* x2 = (const float*)d_in[1];
    const float* w1 = (const float*)d_in[2];
    const float* w2 = (const float*)d_in[3];
    const float* w3 = (const float*)d_in[4];
    const float* w4 = (const float*)d_in[5];
    const float* w5 = (const float*)d_in[6];
    const float* w6 = (const float*)d_in[7];
    float* out = (float*)d_out;

    cudaFuncSetAttribute(tp_gemm, cudaFuncAttributeMaxDynamicSharedMemorySize, SMEM_BYTES);
    precompute_T<<<128, 256>>>(x1, x2);
    tp_gemm<<<512, 256, SMEM_BYTES>>>(w1, w2, w3, w4, w5, w6, out);
}

// round 7
// speedup vs baseline: 1.0024x; 1.0024x over previous
#include <cuda_runtime.h>
#include <cuda_fp16.h>
#include <cstdint>
#include <cstddef>

#define KTOT 4096

// T precomputed in fp16: 2048 rows x 4096 (u,v) cols (16 MB, L2-resident).
__device__ __half g_T[2048 * KTOT];
// All six weights converted to fp16, packed: w1,w2,w3,w4 (33554432 each), w5,w6 (16777216 each).
#define W16_TOTAL 167772160
__device__ __half g_W16[W16_TOTAL];

__device__ __forceinline__ uint32_t smem_u32(const void* p) {
    uint32_t a;
    asm("{ .reg .u64 t; cvta.to.shared.u64 t, %1; cvt.u32.u64 %0, t; }" : "=r"(a) : "l"(p));
    return a;
}
#define CP_ASYNC16(dst, src) \
    asm volatile("cp.async.cg.shared.global [%0], [%1], 16;" :: "r"(dst), "l"(src) : "memory")
#define CP_COMMIT() asm volatile("cp.async.commit_group;" ::: "memory")
#define CP_WAIT2()  asm volatile("cp.async.wait_group 2;" ::: "memory")
#define LDSM_X4(r, addr) \
    asm volatile("ldmatrix.sync.aligned.m8n8.x4.shared.b16 {%0,%1,%2,%3}, [%4];" \
        : "=r"((r)[0]), "=r"((r)[1]), "=r"((r)[2]), "=r"((r)[3]) : "r"(addr))
#define LDSM_X4_T(r, addr) \
    asm volatile("ldmatrix.sync.aligned.m8n8.x4.trans.shared.b16 {%0,%1,%2,%3}, [%4];" \
        : "=r"((r)[0]), "=r"((r)[1]), "=r"((r)[2]), "=r"((r)[3]) : "r"(addr))
#define MMA16816(d, a, b) \
    asm volatile("mma.sync.aligned.m16n8k16.row.col.f32.f16.f16.f32 " \
        "{%0,%1,%2,%3}, {%4,%5,%6,%7}, {%8,%9}, {%0,%1,%2,%3};" \
        : "+f"((d)[0]), "+f"((d)[1]), "+f"((d)[2]), "+f"((d)[3]) \
        : "r"((a)[0]), "r"((a)[1]), "r"((a)[2]), "r"((a)[3]), "r"((b)[0]), "r"((b)[1]))

// ---------------- weight fp32 -> fp16 streaming convert ----------------
// Each thread: 8 halves (2x LDG.128 fp32 -> 1x STG.128 fp16). Block = 2048 halves.
__global__ void __launch_bounds__(256)
convert_w(const float* __restrict__ w1, const float* __restrict__ w2,
          const float* __restrict__ w3, const float* __restrict__ w4,
          const float* __restrict__ w5, const float* __restrict__ w6) {
    size_t idx = (size_t)blockIdx.x * 2048 + (size_t)threadIdx.x * 8;
    const float* src;
    size_t off;
    if      (idx <  33554432ULL) { src = w1; off = idx; }
    else if (idx <  67108864ULL) { src = w2; off = idx -  33554432ULL; }
    else if (idx < 100663296ULL) { src = w3; off = idx -  67108864ULL; }
    else if (idx < 134217728ULL) { src = w4; off = idx - 100663296ULL; }
    else if (idx < 150994944ULL) { src = w5; off = idx - 134217728ULL; }
    else                         { src = w6; off = idx - 150994944ULL; }
    float4 f0 = *(const float4*)(src + off);
    float4 f1 = *(const float4*)(src + off + 4);
    __half2 h0 = __floats2half2_rn(f0.x, f0.y);
    __half2 h1 = __floats2half2_rn(f0.z, f0.w);
    __half2 h2 = __floats2half2_rn(f1.x, f1.y);
    __half2 h3 = __floats2half2_rn(f1.z, f1.w);
    uint4 v;
    v.x = *(uint32_t*)&h0; v.y = *(uint32_t*)&h1;
    v.z = *(uint32_t*)&h2; v.w = *(uint32_t*)&h3;
    *(uint4*)(g_W16 + idx) = v;
}

// ---------------- precompute T (fp16) ----------------
__global__ void precompute_T(const float* __restrict__ x1, const float* __restrict__ x2) {
    __shared__ float sa0[64], sb0[64], sa1[192], sb1[192];
    int b = blockIdx.x, tid = threadIdx.x;
    if (tid < 64) { sa0[tid] = x1[b * 256 + tid]; sb0[tid] = x2[b * 256 + tid]; }
    else { int j = tid - 64; sa1[j] = x1[b * 256 + 64 + j]; sb1[j] = x2[b * 256 + 64 + j]; }
    __syncthreads();

    const float C1 = 0.011048543456039806f;    // 1/sqrt(8192)
    const float C2 = -0.0063788657f;           // -1/sqrt(3*8192)
    const float IS2 = 0.70710678118654752f;
    const float IS6 = 0.40824829046386302f;
    const float INV64 = 0.015625f;

    for (int uv = tid; uv < KTOT; uv += blockDim.x) {
        int u = uv >> 6, v = uv & 63;
        float a0 = sa0[u], b0 = sb0[v];
        float av[3], bv[3];
#pragma unroll
        for (int i = 0; i < 3; i++) { av[i] = sa1[u * 3 + i]; bv[i] = sb1[v * 3 + i]; }
        __half* T = g_T + uv;
        T[(size_t)(0 + b) * KTOT]   = __float2half_rn(C1 * a0 * b0);
        T[(size_t)(128 + b) * KTOT] = __float2half_rn(C2 * (av[0]*bv[0] + av[1]*bv[1] + av[2]*bv[2]));
#pragma unroll
        for (int k = 0; k < 3; k++) {
            int k1 = (k + 1) % 3, k2 = (k + 2) % 3;
            T[(size_t)(256 + k * 128 + b) * KTOT]  = __float2half_rn(C1 * a0 * bv[k]);
            T[(size_t)(640 + k * 128 + b) * KTOT]  = __float2half_rn(C1 * av[k] * b0);
            T[(size_t)(1024 + k * 128 + b) * KTOT] = __float2half_rn(-C1 * (av[k1]*bv[k2] - av[k2]*bv[k1]));
        }
        float q[5];
        q[0] = IS2 * (av[0]*bv[2] + av[2]*bv[0]);
        q[1] = IS2 * (av[0]*bv[1] + av[1]*bv[0]);
        q[2] = IS6 * (2.0f*av[1]*bv[1] - av[0]*bv[0] - av[2]*bv[2]);
        q[3] = IS2 * (av[1]*bv[2] + av[2]*bv[1]);
        q[4] = IS2 * (av[2]*bv[2] - av[0]*bv[0]);
#pragma unroll
        for (int k = 0; k < 5; k++)
            T[(size_t)(1408 + k * 128 + b) * KTOT] = __float2half_rn(INV64 * q[k]);
    }
}

// ---------------- HMMA GEMM (pure fp16, 4-stage cp.async) ----------------
// smem (dynamic): As 4 stages x 128 rows x 80B = 40960; B16 @40960, 4 stages x 32 x 272B = 34816
#define SM_A   0
#define SM_B16 40960
#define SMEM_BYTES 75776
#define KC 32

__global__ void __launch_bounds__(256, 2)
tp_gemm(float* __restrict__ out) {
    extern __shared__ char smem[];
    uint32_t sb = smem_u32(smem);
    int tid = threadIdx.x, wid = tid >> 5, lane = tid & 31;
    int warpM = wid >> 2, warpN = wid & 3;

    // ---- decode work ----
    int bid = blockIdx.x;
    int npass, trow0, trow1 = 0, Ngrp, n0, obase, ncomp, kc;
    size_t wofsA, wofsB = 0;
    if (bid < 64) {                 // o0: 1x64 tiles, w1+w2
        npass = 2; trow0 = 0; trow1 = 128; wofsA = 0; wofsB = 33554432ULL;
        Ngrp = 8192; n0 = bid * 128; obase = 0; ncomp = 1; kc = 0;
    } else if (bid < 256) {         // o1: 3x64 tiles, w3+w4
        int r = bid - 64; int nt = r / 3, mt = r % 3;
        npass = 2; trow0 = 256 + mt * 128; trow1 = 640 + mt * 128;
        wofsA = 67108864ULL; wofsB = 100663296ULL;
        Ngrp = 8192; n0 = nt * 128; obase = 8192; ncomp = 3; kc = mt;
    } else if (bid < 352) {         // o1e: 3x32 tiles, w5
        int r = bid - 256; int nt = r / 3, mt = r % 3;
        npass = 1; trow0 = 1024 + mt * 128; wofsA = 134217728ULL;
        Ngrp = 4096; n0 = nt * 128; obase = 32768; ncomp = 3; kc = mt;
    } else {                        // o2e: 5x32 tiles, w6
        int r = bid - 352; int nt = r / 5, mt = r % 5;
        npass = 1; trow0 = 1408 + mt * 128; wofsA = 150994944ULL;
        Ngrp = 4096; n0 = nt * 128; obase = 45056; ncomp = 5; kc = mt;
    }
    int nch = npass * (KTOT / KC);  // 128 or 256

    // ---- async load of one chunk into stage s (A + B fp16) ----
    auto issue_chunk = [&](int chunk, int s) {
        int pass = chunk >> 7;
        int k0 = (chunk & 127) * KC;
        int trow = pass ? trow1 : trow0;
        const __half* Wh = g_W16 + (pass ? wofsB : wofsA);
        // A: 128 x 32 halves (512 x 16B)
#pragma unroll
        for (int it = 0; it < 2; it++) {
            int idx = tid + it * 256;
            int row = idx >> 2, c = idx & 3;
            const void* src = g_T + ((size_t)(trow + row) * KTOT + k0 + c * 8);
            CP_ASYNC16(sb + SM_A + s * 10240 + row * 80 + c * 16, src);
        }
        // B: 32 x 128 halves (512 x 16B)
#pragma unroll
        for (int it = 0; it < 2; it++) {
            int idx = tid + it * 256;
            int r = idx >> 4, c = idx & 15;
            const void* src = Wh + ((size_t)(k0 + r) * Ngrp + n0 + c * 8);
            CP_ASYNC16(sb + SM_B16 + s * 8704 + r * 272 + c * 16, src);
        }
        CP_COMMIT();
    };

    float acc[4][4][4];
#pragma unroll
    for (int i = 0; i < 4; i++)
#pragma unroll
        for (int j = 0; j < 4; j++)
#pragma unroll
            for (int c = 0; c < 4; c++) acc[i][j][c] = 0.0f;

    // prologue: 3 chunks in flight
    issue_chunk(0, 0);
    issue_chunk(1, 1);
    issue_chunk(2, 2);

    for (int i = 0; i < nch; i++) {
        int s = i & 3;
        CP_WAIT2();            // chunk i complete (<=2 newer groups in flight)
        __syncthreads();       // visibility + protects stage (i-1)%4 from overwrite
        if (i + 3 < nch) issue_chunk(i + 3, (i + 3) & 3);
        else CP_COMMIT();      // keep group accounting uniform
        uint32_t aBase = sb + SM_A + s * 10240;
        uint32_t bBase = sb + SM_B16 + s * 8704;
#pragma unroll
        for (int k16 = 0; k16 < 2; k16++) {
            uint32_t afr[4][4], bfr[2][4];
#pragma unroll
            for (int mi = 0; mi < 4; mi++)
                LDSM_X4(afr[mi], aBase + (warpM * 64 + mi * 16 + (lane & 15)) * 80
                                       + k16 * 32 + (lane >> 4) * 16);
#pragma unroll
            for (int ni = 0; ni < 2; ni++)
                LDSM_X4_T(bfr[ni], bBase + (k16 * 16 + (lane & 15)) * 272
                                        + (warpN * 32 + ni * 16 + (lane >> 4) * 8) * 2);
#pragma unroll
            for (int mi = 0; mi < 4; mi++)
#pragma unroll
                for (int j = 0; j < 4; j++)
                    MMA16816(acc[mi][j], afr[mi], &bfr[j >> 1][(j & 1) * 2]);
        }
    }

    // ---- epilogue: acc -> out ----
#pragma unroll
    for (int mi = 0; mi < 4; mi++) {
        int r0 = warpM * 64 + mi * 16 + (lane >> 2);   // = batch index b
#pragma unroll
        for (int j = 0; j < 4; j++) {
            int n = n0 + warpN * 32 + j * 8 + (lane & 3) * 2;
            size_t b0 = (size_t)r0 * 65536 + obase + kc;
            size_t b1 = (size_t)(r0 + 8) * 65536 + obase + kc;
            out[b0 + (size_t)n * ncomp]       = acc[mi][j][0];
            out[b0 + (size_t)(n + 1) * ncomp] = acc[mi][j][1];
            out[b1 + (size_t)n * ncomp]       = acc[mi][j][2];
            out[b1 + (size_t)(n + 1) * ncomp] = acc[mi][j][3];
        }
    }
}

extern "C" void kernel_launch(void* const* d_in, const int* in_sizes, int n_in,
                              void* d_out, int out_size) {
    const float* x1 = (const float*)d_in[0];
    const float* x2 = (const float*)d_in[1];
    const float* w1 = (const float*)d_in[2];
    const float* w2 = (const float*)d_in[3];
    const float* w3 = (const float*)d_in[4];
    const float* w4 = (const float*)d_in[5];
    const float* w5 = (const float*)d_in[6];
    const float* w6 = (const float*)d_in[7];
    float* out = (float*)d_out;

    cudaFuncSetAttribute(tp_gemm, cudaFuncAttributeMaxDynamicSharedMemorySize, SMEM_BYTES);
    convert_w<<<W16_TOTAL / 2048, 256>>>(w1, w2, w3, w4, w5, w6);
    precompute_T<<<128, 256>>>(x1, x2);
    tp_gemm<<<512, 256, SMEM_BYTES>>>(out);
}